// round 6
// baseline (speedup 1.0000x reference)
#include <cuda_runtime.h>
#include <cuda_bf16.h>
#include <math.h>

// NeuralNDCG, N=4096. Persistent kernel, 128 blocks x 1024 threads.
// mat_t = diag(R) U diag(C); U = exp(c_i p_j - B_j - m_i) fixed bf16 (32MB,
// L2-resident, clean). Per iteration, per 8-row chunk: row-dots (L2 sweep) ->
// finalize R -> immediate re-read (L1-hot, 64KB) for colsums. Colsums go to 8
// RED buckets (contention /4); prologue sums buckets. Tree grid barrier.

#define NNV 4096
#define NBLK 128
#define TPB 1024
#define ROWS_PB 32
#define HROWS 16
#define CH 8                 // rows per chunk
#define NB 8                 // RED buckets
#define EPSF 1e-10f
#define ITERS 50

__device__ __nv_bfloat16 g_mat[(size_t)NNV * NNV];   // 32 MB
__device__ float g_Bv[NNV];
__device__ float g_Rb[2][NNV];
__device__ float g_Cb[2][NNV];
__device__ float g_av[3][NB][NNV];                    // bucketed colsums, 3-rotation
__device__ float g_rowdcg[NNV];
__device__ float g_idcgPart[NBLK];
__device__ unsigned g_leaf[16 * 32];                  // padded leaf counters
__device__ unsigned g_root;
__device__ volatile unsigned g_gen;

__device__ __forceinline__ void grid_barrier(int bid) {
    __syncthreads();
    if (threadIdx.x == 0) {
        __threadfence();
        unsigned mygen = g_gen;
        unsigned l = (unsigned)(bid & 15) * 32;
        if (atomicAdd(&g_leaf[l], 1u) == 7) {          // 8 blocks per leaf
            atomicExch(&g_leaf[l], 0u);
            if (atomicAdd(&g_root, 1u) == 15) {        // 16 leaves
                atomicExch(&g_root, 0u);
                __threadfence();
                g_gen = mygen + 1;
            }
        }
        while (g_gen == mygen) __nanosleep(32);
        __threadfence();
    }
    __syncthreads();
}

__device__ __forceinline__ void half_sync(int h) {
    asm volatile("bar.sync %0, 512;" :: "r"(h + 1) : "memory");
}

__device__ __forceinline__ float wredsum(float v) {
    #pragma unroll
    for (int o = 16; o > 0; o >>= 1) v += __shfl_xor_sync(0xffffffffu, v, o);
    return v;
}
__device__ __forceinline__ float wredmax(float v) {
    #pragma unroll
    for (int o = 16; o > 0; o >>= 1) v = fmaxf(v, __shfl_xor_sync(0xffffffffu, v, o));
    return v;
}
__device__ __forceinline__ void unpack8(uint4 q, float* v) {
    const __nv_bfloat162* hh = reinterpret_cast<const __nv_bfloat162*>(&q);
    #pragma unroll
    for (int p = 0; p < 4; p++) {
        float2 f = __bfloat1622float2(hh[p]);
        v[2 * p] = f.x; v[2 * p + 1] = f.y;
    }
}

__global__ void __launch_bounds__(TPB, 1)
ndcg_kernel(const float* __restrict__ pred, const float* __restrict__ target,
            float* __restrict__ out)
{
    __shared__ float s_buf[2 * NNV];        // 32KB staging (init/build/last-iter)
    __shared__ float s_pb[2][CH][17];       // per-chunk warp partials
    __shared__ float s_rn[2][CH];
    __shared__ float s_red[32];

    const int tid = threadIdx.x, bid = blockIdx.x;
    const int wid = tid >> 5, lane = tid & 31;
    const int h = tid >> 9, ht = tid & 511;
    const int hw = wid & 15;
    const int bkt = (2 * bid + h) & (NB - 1);

    float* p_s = s_buf;
    float* t_s = s_buf + NNV;

    // ================= INIT: zero bucket sets 0,1; C0=1; B[j]; ideal DCG ====
    {
        float4 z4 = make_float4(0.f, 0.f, 0.f, 0.f);
        if (tid < 128)                       // 2 sets * 8 * 4096 floats = 16384 f4
            reinterpret_cast<float4*>(&g_av[0][0][0])[bid * 128 + tid] = z4;
        if (bid < 4) g_Cb[0][bid * 1024 + tid] = 1.0f;
    }
    for (int k = tid; k < NNV; k += TPB) { p_s[k] = pred[k]; t_s[k] = target[k]; }
    __syncthreads();
    {
        int j = bid * ROWS_PB + wid;         // warp per j
        float pj = p_s[j], tj = t_s[j];
        float acc = 0.0f; int rank = 0;
        #pragma unroll 4
        for (int k = 0; k < 128; k++) {
            acc += fabsf(pj - p_s[k * 32 + lane]);
            rank += (t_s[k * 32 + lane] > tj);
        }
        acc = wredsum(acc);
        #pragma unroll
        for (int o = 16; o > 0; o >>= 1) rank += __shfl_xor_sync(0xffffffffu, rank, o);
        if (lane == 0) {
            g_Bv[j] = acc;
            s_red[wid] = (exp2f(tj) - 1.0f) / log2f((float)rank + 2.0f);
        }
        __syncthreads();
        if (tid == 0) {
            float s = 0.0f;
            for (int k = 0; k < 32; k++) s += s_red[k];
            g_idcgPart[bid] = s;
        }
    }
    grid_barrier(bid);

    // ================= BUILD U (bf16), R0 = 1/Z (warp per row) =============
    for (int k = tid; k < NNV; k += TPB) t_s[k] = __ldcg(&g_Bv[k]);
    __syncthreads();
    {
        int i = bid * ROWS_PB + wid;
        float ci = (float)(NNV - 1 - 2 * i);
        float m = -INFINITY;
        for (int c = 0; c < 16; c++) {
            int j0 = (c * 32 + lane) * 8;
            #pragma unroll
            for (int mm = 0; mm < 8; mm++)
                m = fmaxf(m, fmaf(ci, p_s[j0 + mm], -t_s[j0 + mm]));
        }
        m = wredmax(m);
        float z = 0.0f;
        uint4* rq = reinterpret_cast<uint4*>(g_mat + (size_t)i * NNV);
        for (int c = 0; c < 16; c++) {
            int j0 = (c * 32 + lane) * 8;
            float e[8];
            #pragma unroll
            for (int mm = 0; mm < 8; mm++) {
                e[mm] = __expf(fmaf(ci, p_s[j0 + mm], -t_s[j0 + mm]) - m);
                z += e[mm];
            }
            uint4 q;
            __nv_bfloat162* hq = reinterpret_cast<__nv_bfloat162*>(&q);
            hq[0] = __floats2bfloat162_rn(e[0], e[1]);
            hq[1] = __floats2bfloat162_rn(e[2], e[3]);
            hq[2] = __floats2bfloat162_rn(e[4], e[5]);
            hq[3] = __floats2bfloat162_rn(e[6], e[7]);
            rq[c * 32 + lane] = q;
        }
        z = wredsum(z);
        if (lane == 0) g_Rb[0][i] = 1.0f / z;
    }
    grid_barrier(bid);

    // ================= BOOTSTRAP a0 = U^T R0 (into bucket set 0) ===========
    {
        const int rbase = bid * ROWS_PB + h * HROWS;
        float colacc[8];
        #pragma unroll
        for (int mm = 0; mm < 8; mm++) colacc[mm] = 0.0f;
        #pragma unroll 4
        for (int r = 0; r < HROWS; r++) {
            float Ri = __ldcg(&g_Rb[0][rbase + r]);
            uint4 q = reinterpret_cast<const uint4*>(g_mat + (size_t)(rbase + r) * NNV)[ht];
            float v[8]; unpack8(q, v);
            #pragma unroll
            for (int mm = 0; mm < 8; mm++) colacc[mm] = fmaf(Ri, v[mm], colacc[mm]);
        }
        #pragma unroll
        for (int mm = 0; mm < 8; mm++)
            atomicAdd(&g_av[0][bkt][ht * 8 + mm], colacc[mm]);
    }
    grid_barrier(bid);

    // ================= 50 SINKHORN ITERATIONS ==============================
    for (int t = 0; t < ITERS; t++) {
        const bool last = (t == ITERS - 1);
        const float (*a_rd)[NNV] = g_av[t % 3];
        float (*a_wr)[NNV]       = g_av[(t + 1) % 3];
        float* a_zero            = &g_av[(t + 2) % 3][0][0];
        const float* C_rd = g_Cb[t & 1];
        float* C_wr       = g_Cb[(t + 1) & 1];
        const float* R_rd = g_Rb[t & 1];
        float* R_wr       = g_Rb[(t + 1) & 1];
        const int rbase = bid * ROWS_PB + h * HROWS;

        // prologue: a_j = sum of 8 buckets; c' for my 8 columns -> registers
        float cs_r[8];
        {
            float a8[8];
            #pragma unroll
            for (int mm = 0; mm < 8; mm++) a8[mm] = 0.0f;
            #pragma unroll
            for (int b = 0; b < NB; b++) {
                const float4* bp = reinterpret_cast<const float4*>(&a_rd[b][ht * 8]);
                float4 x0 = __ldcg(bp), x1 = __ldcg(bp + 1);
                a8[0] += x0.x; a8[1] += x0.y; a8[2] += x0.z; a8[3] += x0.w;
                a8[4] += x1.x; a8[5] += x1.y; a8[6] += x1.z; a8[7] += x1.w;
            }
            const float4* cp = reinterpret_cast<const float4*>(C_rd + ht * 8);
            float4 c0 = __ldcg(cp), c1 = __ldcg(cp + 1);
            cs_r[0] = c0.x / fmaxf(c0.x * a8[0], EPSF);
            cs_r[1] = c0.y / fmaxf(c0.y * a8[1], EPSF);
            cs_r[2] = c0.z / fmaxf(c0.z * a8[2], EPSF);
            cs_r[3] = c0.w / fmaxf(c0.w * a8[3], EPSF);
            cs_r[4] = c1.x / fmaxf(c1.x * a8[4], EPSF);
            cs_r[5] = c1.y / fmaxf(c1.y * a8[5], EPSF);
            cs_r[6] = c1.z / fmaxf(c1.z * a8[6], EPSF);
            cs_r[7] = c1.w / fmaxf(c1.w * a8[7], EPSF);
        }
        if (tid < ROWS_PB) {
            int j = bid * ROWS_PB + tid;
            float Cj = __ldcg(&C_rd[j]);
            float aj = 0.0f;
            #pragma unroll
            for (int b = 0; b < NB; b++) aj += __ldcg(&a_rd[b][j]);
            C_wr[j] = Cj / fmaxf(Cj * aj, EPSF);
        }
        if (!last && tid < 64)               // zero 256 floats of set (t+2)
            reinterpret_cast<float4*>(a_zero)[bid * 64 + tid] =
                make_float4(0.f, 0.f, 0.f, 0.f);

        if (!last) {
            float colacc[8];
            #pragma unroll
            for (int mm = 0; mm < 8; mm++) colacc[mm] = 0.0f;
            #pragma unroll
            for (int c = 0; c < HROWS / CH; c++) {
                const int cb = rbase + c * CH;
                // pass 1: row dots for this 64KB chunk (L2)
                #pragma unroll
                for (int r = 0; r < CH; r++) {
                    uint4 q = reinterpret_cast<const uint4*>(g_mat + (size_t)(cb + r) * NNV)[ht];
                    float v[8]; unpack8(q, v);
                    float d = 0.0f;
                    #pragma unroll
                    for (int mm = 0; mm < 8; mm++) d = fmaf(v[mm], cs_r[mm], d);
                    d = wredsum(d);
                    if (lane == 0) s_pb[h][r][hw] = d;
                }
                half_sync(h);
                if (ht < CH) {
                    int i = cb + ht;
                    float b = 0.0f;
                    #pragma unroll
                    for (int k = 0; k < 16; k++) b += s_pb[h][ht][k];
                    float Ro = __ldcg(&R_rd[i]);
                    float Rn = Ro / fmaxf(Ro * b, EPSF);
                    R_wr[i] = Rn;
                    s_rn[h][ht] = Rn;
                }
                half_sync(h);
                // pass 2: immediate re-read of the hot chunk (L1)
                #pragma unroll
                for (int r = 0; r < CH; r++) {
                    uint4 q = reinterpret_cast<const uint4*>(g_mat + (size_t)(cb + r) * NNV)[ht];
                    float v[8]; unpack8(q, v);
                    float Rn = s_rn[h][r];
                    #pragma unroll
                    for (int mm = 0; mm < 8; mm++) colacc[mm] = fmaf(Rn, v[mm], colacc[mm]);
                }
            }
            #pragma unroll
            for (int mm = 0; mm < 8; mm++)
                atomicAdd(&a_wr[bkt][ht * 8 + mm], colacc[mm]);
        } else {
            // last iteration: fold DCG contraction, chunked
            float gs_r[8];
            #pragma unroll
            for (int mm = 0; mm < 8; mm++)
                gs_r[mm] = cs_r[mm] * (exp2f(target[ht * 8 + mm]) - 1.0f);
            #pragma unroll
            for (int c = 0; c < HROWS / CH; c++) {
                const int cb = rbase + c * CH;
                #pragma unroll
                for (int r = 0; r < CH; r++) {
                    uint4 q = reinterpret_cast<const uint4*>(g_mat + (size_t)(cb + r) * NNV)[ht];
                    float v[8]; unpack8(q, v);
                    float d1 = 0.0f, d2 = 0.0f;
                    #pragma unroll
                    for (int mm = 0; mm < 8; mm++) {
                        d1 = fmaf(v[mm], cs_r[mm], d1);
                        d2 = fmaf(v[mm], gs_r[mm], d2);
                    }
                    d1 = wredsum(d1);
                    d2 = wredsum(d2);
                    if (lane == 0) s_pb[h][r][hw] = d1;
                    if (lane == 1) s_buf[(h * CH + r) * 16 + hw] = d2;
                }
                half_sync(h);
                if (ht < CH) {
                    int i = cb + ht;
                    float b = 0.0f, d = 0.0f;
                    #pragma unroll
                    for (int k = 0; k < 16; k++) {
                        b += s_pb[h][ht][k];
                        d += s_buf[(h * CH + ht) * 16 + k];
                    }
                    float Ro = __ldcg(&R_rd[i]);
                    float Rn = Ro / fmaxf(Ro * b, EPSF);
                    g_rowdcg[i] = Rn * d / log2f((float)i + 2.0f);
                }
                half_sync(h);
            }
        }
        grid_barrier(bid);
    }

    // ================= FINAL ==============================================
    if (bid == 0) {
        float part = 0.0f;
        #pragma unroll
        for (int k = 0; k < 4; k++) part += __ldcg(&g_rowdcg[tid * 4 + k]);
        part = wredsum(part);
        if (lane == 0) s_red[wid] = part;
        __syncthreads();
        if (tid == 0) {
            float dcg = 0.0f;
            for (int k = 0; k < 32; k++) dcg += s_red[k];
            float idcg = 0.0f;
            for (int k = 0; k < NBLK; k++) idcg += __ldcg(&g_idcgPart[k]);
            out[0] = -(dcg / (idcg + 1e-8f));
        }
    }
}

extern "C" void kernel_launch(void* const* d_in, const int* in_sizes, int n_in,
                              void* d_out, int out_size) {
    const float* pred   = (const float*)d_in[0];
    const float* target = (const float*)d_in[1];
    float* out = (float*)d_out;
    ndcg_kernel<<<NBLK, TPB>>>(pred, target, out);
}

// round 7
// speedup vs baseline: 1.1513x; 1.1513x over previous
#include <cuda_runtime.h>
#include <cuda_bf16.h>
#include <math.h>

// NeuralNDCG, N=4096. Persistent kernel, 256 blocks x 512 threads
// (2 blocks/SM co-resident -> cross-block latency hiding at sync points).
// mat_t = diag(R) U diag(C); U = exp(c_i p_j - B_j - m_i) fixed bf16 (32MB,
// L2-resident, read-only). Per iteration, per 8-row chunk: row-dots (L2) ->
// finalize R -> immediate chunk re-read (L1) for colsums. Colsums -> 8 RED
// buckets; prologue sums buckets. Tree grid barrier (16 leaves x 16).

#define NNV 4096
#define NBLK 256
#define TPB 512
#define ROWS_PB 16
#define CH 8
#define NB 8
#define EPSF 1e-10f
#define ITERS 50

__device__ __nv_bfloat16 g_mat[(size_t)NNV * NNV];   // 32 MB
__device__ float g_Bv[NNV];
__device__ float g_Rb[2][NNV];
__device__ float g_Cb[2][NNV];
__device__ float g_av[3][NB][NNV];                    // bucketed colsums
__device__ float g_rowdcg[NNV];
__device__ float g_idcgPart[NBLK];
__device__ unsigned g_leaf[16 * 32];
__device__ unsigned g_root;
__device__ volatile unsigned g_gen;

__device__ __forceinline__ void grid_barrier(int bid) {
    __syncthreads();
    if (threadIdx.x == 0) {
        __threadfence();
        unsigned mygen = g_gen;
        unsigned l = (unsigned)(bid & 15) * 32;
        if (atomicAdd(&g_leaf[l], 1u) == 15) {         // 16 blocks per leaf
            atomicExch(&g_leaf[l], 0u);
            if (atomicAdd(&g_root, 1u) == 15) {        // 16 leaves
                atomicExch(&g_root, 0u);
                __threadfence();
                g_gen = mygen + 1;
            }
        }
        while (g_gen == mygen) __nanosleep(32);
        __threadfence();
    }
    __syncthreads();
}

__device__ __forceinline__ float wredsum(float v) {
    #pragma unroll
    for (int o = 16; o > 0; o >>= 1) v += __shfl_xor_sync(0xffffffffu, v, o);
    return v;
}
__device__ __forceinline__ float wredmax(float v) {
    #pragma unroll
    for (int o = 16; o > 0; o >>= 1) v = fmaxf(v, __shfl_xor_sync(0xffffffffu, v, o));
    return v;
}
__device__ __forceinline__ void unpack8(uint4 q, float* v) {
    const __nv_bfloat162* hh = reinterpret_cast<const __nv_bfloat162*>(&q);
    #pragma unroll
    for (int p = 0; p < 4; p++) {
        float2 f = __bfloat1622float2(hh[p]);
        v[2 * p] = f.x; v[2 * p + 1] = f.y;
    }
}

__global__ void __launch_bounds__(TPB, 2)
ndcg_kernel(const float* __restrict__ pred, const float* __restrict__ target,
            float* __restrict__ out)
{
    __shared__ float s_buf[2 * NNV];       // 32KB staging (init/build/last-iter)
    __shared__ float s_pb[CH][17];         // per-chunk warp partials
    __shared__ float s_pd[CH][17];
    __shared__ float s_rn[CH];
    __shared__ float s_red[16];

    const int tid = threadIdx.x, bid = blockIdx.x;
    const int wid = tid >> 5, lane = tid & 31;
    const int bkt = bid & (NB - 1);
    const int rbase = bid * ROWS_PB;

    float* p_s = s_buf;
    float* t_s = s_buf + NNV;

    // ================= INIT: zero bucket sets 0,1; C0=1; B[j]; ideal DCG ====
    {
        float4 z4 = make_float4(0.f, 0.f, 0.f, 0.f);
        if (tid < 64)                        // 2 sets * 8 * 4096 = 16384 f4
            reinterpret_cast<float4*>(&g_av[0][0][0])[bid * 64 + tid] = z4;
        if (bid < 8) g_Cb[0][bid * TPB + tid] = 1.0f;
    }
    for (int k = tid; k < NNV; k += TPB) { p_s[k] = pred[k]; t_s[k] = target[k]; }
    __syncthreads();
    {
        int j = rbase + wid;                 // warp per j, 16 j per block
        float pj = p_s[j], tj = t_s[j];
        float acc = 0.0f; int rank = 0;
        #pragma unroll 4
        for (int k = 0; k < 128; k++) {
            acc += fabsf(pj - p_s[k * 32 + lane]);
            rank += (t_s[k * 32 + lane] > tj);
        }
        acc = wredsum(acc);
        #pragma unroll
        for (int o = 16; o > 0; o >>= 1) rank += __shfl_xor_sync(0xffffffffu, rank, o);
        if (lane == 0) {
            g_Bv[j] = acc;
            s_red[wid] = (exp2f(tj) - 1.0f) / log2f((float)rank + 2.0f);
        }
        __syncthreads();
        if (tid == 0) {
            float s = 0.0f;
            for (int k = 0; k < 16; k++) s += s_red[k];
            g_idcgPart[bid] = s;
        }
    }
    grid_barrier(bid);

    // ================= BUILD U (bf16), R0 = 1/Z (warp per row) =============
    for (int k = tid; k < NNV; k += TPB) t_s[k] = __ldcg(&g_Bv[k]);
    __syncthreads();
    {
        int i = rbase + wid;
        float ci = (float)(NNV - 1 - 2 * i);
        float m = -INFINITY;
        for (int c = 0; c < 16; c++) {
            int j0 = (c * 32 + lane) * 8;
            #pragma unroll
            for (int mm = 0; mm < 8; mm++)
                m = fmaxf(m, fmaf(ci, p_s[j0 + mm], -t_s[j0 + mm]));
        }
        m = wredmax(m);
        float z = 0.0f;
        uint4* rq = reinterpret_cast<uint4*>(g_mat + (size_t)i * NNV);
        for (int c = 0; c < 16; c++) {
            int j0 = (c * 32 + lane) * 8;
            float e[8];
            #pragma unroll
            for (int mm = 0; mm < 8; mm++) {
                e[mm] = __expf(fmaf(ci, p_s[j0 + mm], -t_s[j0 + mm]) - m);
                z += e[mm];
            }
            uint4 q;
            __nv_bfloat162* hq = reinterpret_cast<__nv_bfloat162*>(&q);
            hq[0] = __floats2bfloat162_rn(e[0], e[1]);
            hq[1] = __floats2bfloat162_rn(e[2], e[3]);
            hq[2] = __floats2bfloat162_rn(e[4], e[5]);
            hq[3] = __floats2bfloat162_rn(e[6], e[7]);
            rq[c * 32 + lane] = q;
        }
        z = wredsum(z);
        if (lane == 0) g_Rb[0][i] = 1.0f / z;
    }
    grid_barrier(bid);

    // ================= BOOTSTRAP a0 = U^T R0 (bucket set 0) ================
    {
        float colacc[8];
        #pragma unroll
        for (int mm = 0; mm < 8; mm++) colacc[mm] = 0.0f;
        #pragma unroll 4
        for (int r = 0; r < ROWS_PB; r++) {
            float Ri = __ldcg(&g_Rb[0][rbase + r]);
            uint4 q = reinterpret_cast<const uint4*>(g_mat + (size_t)(rbase + r) * NNV)[tid];
            float v[8]; unpack8(q, v);
            #pragma unroll
            for (int mm = 0; mm < 8; mm++) colacc[mm] = fmaf(Ri, v[mm], colacc[mm]);
        }
        #pragma unroll
        for (int mm = 0; mm < 8; mm++)
            atomicAdd(&g_av[0][bkt][tid * 8 + mm], colacc[mm]);
    }
    grid_barrier(bid);

    // ================= 50 SINKHORN ITERATIONS ==============================
    for (int t = 0; t < ITERS; t++) {
        const bool last = (t == ITERS - 1);
        const float (*a_rd)[NNV] = g_av[t % 3];
        float (*a_wr)[NNV]       = g_av[(t + 1) % 3];
        float* a_zero            = &g_av[(t + 2) % 3][0][0];
        const float* C_rd = g_Cb[t & 1];
        float* C_wr       = g_Cb[(t + 1) & 1];
        const float* R_rd = g_Rb[t & 1];
        float* R_wr       = g_Rb[(t + 1) & 1];

        // prologue: a_j = sum of buckets; C' for my 8 columns -> registers
        float cs_r[8];
        {
            float a8[8];
            #pragma unroll
            for (int mm = 0; mm < 8; mm++) a8[mm] = 0.0f;
            #pragma unroll
            for (int b = 0; b < NB; b++) {
                const float4* bp = reinterpret_cast<const float4*>(&a_rd[b][tid * 8]);
                float4 x0 = __ldcg(bp), x1 = __ldcg(bp + 1);
                a8[0] += x0.x; a8[1] += x0.y; a8[2] += x0.z; a8[3] += x0.w;
                a8[4] += x1.x; a8[5] += x1.y; a8[6] += x1.z; a8[7] += x1.w;
            }
            const float4* cp = reinterpret_cast<const float4*>(C_rd + tid * 8);
            float4 c0 = __ldcg(cp), c1 = __ldcg(cp + 1);
            cs_r[0] = c0.x / fmaxf(c0.x * a8[0], EPSF);
            cs_r[1] = c0.y / fmaxf(c0.y * a8[1], EPSF);
            cs_r[2] = c0.z / fmaxf(c0.z * a8[2], EPSF);
            cs_r[3] = c0.w / fmaxf(c0.w * a8[3], EPSF);
            cs_r[4] = c1.x / fmaxf(c1.x * a8[4], EPSF);
            cs_r[5] = c1.y / fmaxf(c1.y * a8[5], EPSF);
            cs_r[6] = c1.z / fmaxf(c1.z * a8[6], EPSF);
            cs_r[7] = c1.w / fmaxf(c1.w * a8[7], EPSF);
        }
        if (tid < ROWS_PB) {
            int j = rbase + tid;
            float Cj = __ldcg(&C_rd[j]);
            float aj = 0.0f;
            #pragma unroll
            for (int b = 0; b < NB; b++) aj += __ldcg(&a_rd[b][j]);
            C_wr[j] = Cj / fmaxf(Cj * aj, EPSF);
        }
        if (!last && tid < 32)               // zero my slice of set (t+2)
            reinterpret_cast<float4*>(a_zero)[bid * 32 + tid] =
                make_float4(0.f, 0.f, 0.f, 0.f);

        if (!last) {
            float colacc[8];
            #pragma unroll
            for (int mm = 0; mm < 8; mm++) colacc[mm] = 0.0f;
            #pragma unroll
            for (int c = 0; c < ROWS_PB / CH; c++) {
                const int cb = rbase + c * CH;
                // pass 1: row dots for this 64KB chunk (L2)
                #pragma unroll
                for (int r = 0; r < CH; r++) {
                    uint4 q = reinterpret_cast<const uint4*>(g_mat + (size_t)(cb + r) * NNV)[tid];
                    float v[8]; unpack8(q, v);
                    float d = 0.0f;
                    #pragma unroll
                    for (int mm = 0; mm < 8; mm++) d = fmaf(v[mm], cs_r[mm], d);
                    d = wredsum(d);
                    if (lane == 0) s_pb[r][wid] = d;
                }
                __syncthreads();
                if (tid < CH) {
                    int i = cb + tid;
                    float b = 0.0f;
                    #pragma unroll
                    for (int k = 0; k < 16; k++) b += s_pb[tid][k];
                    float Ro = __ldcg(&R_rd[i]);
                    float Rn = Ro / fmaxf(Ro * b, EPSF);
                    R_wr[i] = Rn;
                    s_rn[tid] = Rn;
                }
                __syncthreads();
                // pass 2: immediate re-read of hot chunk (L1)
                #pragma unroll
                for (int r = 0; r < CH; r++) {
                    uint4 q = reinterpret_cast<const uint4*>(g_mat + (size_t)(cb + r) * NNV)[tid];
                    float v[8]; unpack8(q, v);
                    float Rn = s_rn[r];
                    #pragma unroll
                    for (int mm = 0; mm < 8; mm++) colacc[mm] = fmaf(Rn, v[mm], colacc[mm]);
                }
            }
            #pragma unroll
            for (int mm = 0; mm < 8; mm++)
                atomicAdd(&a_wr[bkt][tid * 8 + mm], colacc[mm]);
        } else {
            // last iteration: fold DCG contraction, chunked
            float gs_r[8];
            #pragma unroll
            for (int mm = 0; mm < 8; mm++)
                gs_r[mm] = cs_r[mm] * (exp2f(target[tid * 8 + mm]) - 1.0f);
            #pragma unroll
            for (int c = 0; c < ROWS_PB / CH; c++) {
                const int cb = rbase + c * CH;
                #pragma unroll
                for (int r = 0; r < CH; r++) {
                    uint4 q = reinterpret_cast<const uint4*>(g_mat + (size_t)(cb + r) * NNV)[tid];
                    float v[8]; unpack8(q, v);
                    float d1 = 0.0f, d2 = 0.0f;
                    #pragma unroll
                    for (int mm = 0; mm < 8; mm++) {
                        d1 = fmaf(v[mm], cs_r[mm], d1);
                        d2 = fmaf(v[mm], gs_r[mm], d2);
                    }
                    d1 = wredsum(d1);
                    d2 = wredsum(d2);
                    if (lane == 0) { s_pb[r][wid] = d1; s_pd[r][wid] = d2; }
                }
                __syncthreads();
                if (tid < CH) {
                    int i = cb + tid;
                    float b = 0.0f, d = 0.0f;
                    #pragma unroll
                    for (int k = 0; k < 16; k++) { b += s_pb[tid][k]; d += s_pd[tid][k]; }
                    float Ro = __ldcg(&R_rd[i]);
                    float Rn = Ro / fmaxf(Ro * b, EPSF);
                    g_rowdcg[i] = Rn * d / log2f((float)i + 2.0f);
                }
                __syncthreads();
            }
        }
        grid_barrier(bid);
    }

    // ================= FINAL ==============================================
    if (bid == 0) {
        float part = 0.0f;
        #pragma unroll
        for (int k = 0; k < 8; k++) part += __ldcg(&g_rowdcg[tid * 8 + k]);
        part = wredsum(part);
        if (lane == 0) s_red[wid] = part;
        __syncthreads();
        if (tid == 0) {
            float dcg = 0.0f;
            for (int k = 0; k < 16; k++) dcg += s_red[k];
            float idcg = 0.0f;
            for (int k = 0; k < NBLK; k++) idcg += __ldcg(&g_idcgPart[k]);
            out[0] = -(dcg / (idcg + 1e-8f));
        }
    }
}

extern "C" void kernel_launch(void* const* d_in, const int* in_sizes, int n_in,
                              void* d_out, int out_size) {
    const float* pred   = (const float*)d_in[0];
    const float* target = (const float*)d_in[1];
    float* out = (float*)d_out;
    ndcg_kernel<<<NBLK, TPB>>>(pred, target, out);
}

// round 8
// speedup vs baseline: 1.4670x; 1.2742x over previous
#include <cuda_runtime.h>
#include <cuda_bf16.h>
#include <math.h>

// NeuralNDCG, N=4096. Persistent kernel, 296 blocks (2/SM exact) x 512 threads.
// mat_t = diag(R) U diag(C); U = exp(c_i p_j - B_j - m_i) fixed bf16. BOTH U
// and U^T stored (64MB, L2-resident). Per iteration: row sweep over U (b_i ->
// R') [barrier] col sweep over U^T (a'_j) [barrier]. Block-local reductions
// only -- zero atomics, zero buckets, zero re-reads.

#define NNV 4096
#define NBLK 296
#define TPB 512
#define MAXR 14
#define EPSF 1e-10f
#define ITERS 50

__device__ __nv_bfloat16 g_mat [(size_t)NNV * NNV];   // U   (32 MB)
__device__ __nv_bfloat16 g_matT[(size_t)NNV * NNV];   // U^T (32 MB)
__device__ float g_Bv[NNV], g_mv[NNV], g_R[NNV], g_a[NNV];
__device__ float g_C[2][NNV];
__device__ float g_rowdcg[NNV];
__device__ float g_idcgPart[NBLK];
__device__ unsigned g_leaf[37 * 32];
__device__ unsigned g_root;
__device__ volatile unsigned g_gen;

__device__ __forceinline__ void grid_barrier(int bid) {
    __syncthreads();
    if (threadIdx.x == 0) {
        __threadfence();
        unsigned mygen = g_gen;
        unsigned l = (unsigned)(bid >> 3) * 32;       // 37 leaves x 8 blocks
        if (atomicAdd(&g_leaf[l], 1u) == 7) {
            atomicExch(&g_leaf[l], 0u);
            if (atomicAdd(&g_root, 1u) == 36) {
                atomicExch(&g_root, 0u);
                __threadfence();
                g_gen = mygen + 1;
            }
        }
        while (g_gen == mygen) __nanosleep(32);
        __threadfence();
    }
    __syncthreads();
}

__device__ __forceinline__ float wredsum(float v) {
    #pragma unroll
    for (int o = 16; o > 0; o >>= 1) v += __shfl_xor_sync(0xffffffffu, v, o);
    return v;
}
__device__ __forceinline__ float wredmax(float v) {
    #pragma unroll
    for (int o = 16; o > 0; o >>= 1) v = fmaxf(v, __shfl_xor_sync(0xffffffffu, v, o));
    return v;
}
__device__ __forceinline__ void unpack8(uint4 q, float* v) {
    const __nv_bfloat162* hh = reinterpret_cast<const __nv_bfloat162*>(&q);
    #pragma unroll
    for (int p = 0; p < 4; p++) {
        float2 f = __bfloat1622float2(hh[p]);
        v[2 * p] = f.x; v[2 * p + 1] = f.y;
    }
}

__global__ void __launch_bounds__(TPB, 2)
ndcg_kernel(const float* __restrict__ pred, const float* __restrict__ target,
            float* __restrict__ out)
{
    __shared__ float p_s[NNV];             // 16KB: pred (persists all phases)
    __shared__ float t_s[NNV];             // 16KB: target, then B
    __shared__ float s_pb[MAXR][17];
    __shared__ float s_pd[MAXR][17];
    __shared__ float s_red[32];

    const int tid = threadIdx.x, bid = blockIdx.x;
    const int wid = tid >> 5, lane = tid & 31;
    // row range: first 248 blocks get 14 rows, last 48 get 13 (total 4096)
    const int start = bid * 13 + (bid < 248 ? bid : 248);
    const int cnt   = 13 + (bid < 248 ? 1 : 0);

    // ================= INIT: C0=1; B[j]; ideal DCG =================
    if (bid < 8) g_C[0][bid * TPB + tid] = 1.0f;
    for (int k = tid; k < NNV; k += TPB) { p_s[k] = pred[k]; t_s[k] = target[k]; }
    __syncthreads();
    if (wid < cnt) {
        int j = start + wid;               // warp per j
        float pj = p_s[j], tj = t_s[j];
        float acc = 0.0f; int rank = 0;
        #pragma unroll 4
        for (int k = 0; k < 128; k++) {
            acc += fabsf(pj - p_s[k * 32 + lane]);
            rank += (t_s[k * 32 + lane] > tj);
        }
        acc = wredsum(acc);
        #pragma unroll
        for (int o = 16; o > 0; o >>= 1) rank += __shfl_xor_sync(0xffffffffu, rank, o);
        if (lane == 0) {
            g_Bv[j] = acc;
            s_red[wid] = (exp2f(tj) - 1.0f) / log2f((float)rank + 2.0f);
        }
    }
    __syncthreads();
    if (tid == 0) {
        float s = 0.0f;
        for (int k = 0; k < cnt; k++) s += s_red[k];
        g_idcgPart[bid] = s;
    }
    grid_barrier(bid);

    // ================= BUILD U (bf16), save m_i, R0=1/Z ====================
    for (int k = tid; k < NNV; k += TPB) t_s[k] = __ldcg(&g_Bv[k]);
    __syncthreads();
    if (wid < cnt) {
        int i = start + wid;
        float ci = (float)(NNV - 1 - 2 * i);
        float m = -INFINITY;
        for (int c = 0; c < 16; c++) {
            int j0 = (c * 32 + lane) * 8;
            #pragma unroll
            for (int mm = 0; mm < 8; mm++)
                m = fmaxf(m, fmaf(ci, p_s[j0 + mm], -t_s[j0 + mm]));
        }
        m = wredmax(m);
        float z = 0.0f;
        uint4* rq = reinterpret_cast<uint4*>(g_mat + (size_t)i * NNV);
        for (int c = 0; c < 16; c++) {
            int j0 = (c * 32 + lane) * 8;
            float e[8];
            #pragma unroll
            for (int mm = 0; mm < 8; mm++) {
                e[mm] = __expf(fmaf(ci, p_s[j0 + mm], -t_s[j0 + mm]) - m);
                z += e[mm];
            }
            uint4 q;
            __nv_bfloat162* hq = reinterpret_cast<__nv_bfloat162*>(&q);
            hq[0] = __floats2bfloat162_rn(e[0], e[1]);
            hq[1] = __floats2bfloat162_rn(e[2], e[3]);
            hq[2] = __floats2bfloat162_rn(e[4], e[5]);
            hq[3] = __floats2bfloat162_rn(e[6], e[7]);
            rq[c * 32 + lane] = q;
        }
        z = wredsum(z);
        if (lane == 0) { g_mv[i] = m; g_R[i] = 1.0f / z; }
    }
    grid_barrier(bid);

    // ================= BUILD U^T rows (recompute) + a0 = U^T R0 ============
    {
        float m_r[8], r0_r[8];
        {
            const float4* mp = reinterpret_cast<const float4*>(&g_mv[tid * 8]);
            const float4* rp = reinterpret_cast<const float4*>(&g_R[tid * 8]);
            float4 m0 = __ldcg(mp), m1 = __ldcg(mp + 1);
            float4 r0 = __ldcg(rp), r1 = __ldcg(rp + 1);
            m_r[0]=m0.x; m_r[1]=m0.y; m_r[2]=m0.z; m_r[3]=m0.w;
            m_r[4]=m1.x; m_r[5]=m1.y; m_r[6]=m1.z; m_r[7]=m1.w;
            r0_r[0]=r0.x; r0_r[1]=r0.y; r0_r[2]=r0.z; r0_r[3]=r0.w;
            r0_r[4]=r1.x; r0_r[5]=r1.y; r0_r[6]=r1.z; r0_r[7]=r1.w;
        }
        float ci_r[8];
        #pragma unroll
        for (int mm = 0; mm < 8; mm++)
            ci_r[mm] = (float)(NNV - 1 - 2 * (tid * 8 + mm));
        for (int r = 0; r < cnt; r++) {
            int j = start + r;
            float pj = p_s[j], Bj = t_s[j];
            float e[8], d = 0.0f;
            #pragma unroll
            for (int mm = 0; mm < 8; mm++) {
                e[mm] = __expf(fmaf(ci_r[mm], pj, -Bj) - m_r[mm]);
                d = fmaf(r0_r[mm], e[mm], d);
            }
            uint4 q;
            __nv_bfloat162* hq = reinterpret_cast<__nv_bfloat162*>(&q);
            hq[0] = __floats2bfloat162_rn(e[0], e[1]);
            hq[1] = __floats2bfloat162_rn(e[2], e[3]);
            hq[2] = __floats2bfloat162_rn(e[4], e[5]);
            hq[3] = __floats2bfloat162_rn(e[6], e[7]);
            reinterpret_cast<uint4*>(g_matT + (size_t)j * NNV)[tid] = q;
            d = wredsum(d);
            if (lane == 0) s_pb[r][wid] = d;
        }
        __syncthreads();
        if (tid < cnt) {
            float a = 0.0f;
            #pragma unroll
            for (int k = 0; k < 16; k++) a += s_pb[tid][k];
            g_a[start + tid] = a;
        }
    }
    grid_barrier(bid);

    // ================= 50 SINKHORN ITERATIONS ==============================
    for (int t = 0; t < ITERS; t++) {
        const bool last = (t == ITERS - 1);
        const float* C_rd = g_C[t & 1];
        float* C_wr       = g_C[(t + 1) & 1];

        // C' for my 8 columns -> registers
        float cs_r[8];
        {
            const float4* cp = reinterpret_cast<const float4*>(C_rd + tid * 8);
            const float4* ap = reinterpret_cast<const float4*>(g_a + tid * 8);
            float4 c0 = __ldcg(cp), c1 = __ldcg(cp + 1);
            float4 a0 = __ldcg(ap), a1 = __ldcg(ap + 1);
            cs_r[0] = c0.x / fmaxf(c0.x * a0.x, EPSF);
            cs_r[1] = c0.y / fmaxf(c0.y * a0.y, EPSF);
            cs_r[2] = c0.z / fmaxf(c0.z * a0.z, EPSF);
            cs_r[3] = c0.w / fmaxf(c0.w * a0.w, EPSF);
            cs_r[4] = c1.x / fmaxf(c1.x * a1.x, EPSF);
            cs_r[5] = c1.y / fmaxf(c1.y * a1.y, EPSF);
            cs_r[6] = c1.z / fmaxf(c1.z * a1.z, EPSF);
            cs_r[7] = c1.w / fmaxf(c1.w * a1.w, EPSF);
        }
        if (!last && tid < cnt) {
            int j = start + tid;
            float Cj = __ldcg(&C_rd[j]), aj = __ldcg(&g_a[j]);
            C_wr[j] = Cj / fmaxf(Cj * aj, EPSF);
        }

        if (!last) {
            // ---- row pass over U: b_i -> R' (2-row batched) ----
            int r = 0;
            for (; r + 1 < cnt; r += 2) {
                uint4 q0 = reinterpret_cast<const uint4*>(g_mat + (size_t)(start + r) * NNV)[tid];
                uint4 q1 = reinterpret_cast<const uint4*>(g_mat + (size_t)(start + r + 1) * NNV)[tid];
                float v0[8], v1[8]; unpack8(q0, v0); unpack8(q1, v1);
                float d0 = 0.0f, d1 = 0.0f;
                #pragma unroll
                for (int mm = 0; mm < 8; mm++) {
                    d0 = fmaf(v0[mm], cs_r[mm], d0);
                    d1 = fmaf(v1[mm], cs_r[mm], d1);
                }
                d0 = wredsum(d0); d1 = wredsum(d1);
                if (lane == 0) { s_pb[r][wid] = d0; s_pb[r + 1][wid] = d1; }
            }
            if (r < cnt) {
                uint4 q0 = reinterpret_cast<const uint4*>(g_mat + (size_t)(start + r) * NNV)[tid];
                float v0[8]; unpack8(q0, v0);
                float d0 = 0.0f;
                #pragma unroll
                for (int mm = 0; mm < 8; mm++) d0 = fmaf(v0[mm], cs_r[mm], d0);
                d0 = wredsum(d0);
                if (lane == 0) s_pb[r][wid] = d0;
            }
            __syncthreads();
            if (tid < cnt) {
                int i = start + tid;
                float b = 0.0f;
                #pragma unroll
                for (int k = 0; k < 16; k++) b += s_pb[tid][k];
                float Ro = g_R[i];
                g_R[i] = Ro / fmaxf(Ro * b, EPSF);
            }
            grid_barrier(bid);

            // ---- col pass over U^T: a'_j (2-row batched) ----
            float rs_r[8];
            {
                const float4* rp = reinterpret_cast<const float4*>(&g_R[tid * 8]);
                float4 r0 = __ldcg(rp), r1 = __ldcg(rp + 1);
                rs_r[0]=r0.x; rs_r[1]=r0.y; rs_r[2]=r0.z; rs_r[3]=r0.w;
                rs_r[4]=r1.x; rs_r[5]=r1.y; rs_r[6]=r1.z; rs_r[7]=r1.w;
            }
            r = 0;
            for (; r + 1 < cnt; r += 2) {
                uint4 q0 = reinterpret_cast<const uint4*>(g_matT + (size_t)(start + r) * NNV)[tid];
                uint4 q1 = reinterpret_cast<const uint4*>(g_matT + (size_t)(start + r + 1) * NNV)[tid];
                float v0[8], v1[8]; unpack8(q0, v0); unpack8(q1, v1);
                float d0 = 0.0f, d1 = 0.0f;
                #pragma unroll
                for (int mm = 0; mm < 8; mm++) {
                    d0 = fmaf(v0[mm], rs_r[mm], d0);
                    d1 = fmaf(v1[mm], rs_r[mm], d1);
                }
                d0 = wredsum(d0); d1 = wredsum(d1);
                if (lane == 0) { s_pb[r][wid] = d0; s_pb[r + 1][wid] = d1; }
            }
            if (r < cnt) {
                uint4 q0 = reinterpret_cast<const uint4*>(g_matT + (size_t)(start + r) * NNV)[tid];
                float v0[8]; unpack8(q0, v0);
                float d0 = 0.0f;
                #pragma unroll
                for (int mm = 0; mm < 8; mm++) d0 = fmaf(v0[mm], rs_r[mm], d0);
                d0 = wredsum(d0);
                if (lane == 0) s_pb[r][wid] = d0;
            }
            __syncthreads();
            if (tid < cnt) {
                float a = 0.0f;
                #pragma unroll
                for (int k = 0; k < 16; k++) a += s_pb[tid][k];
                g_a[start + tid] = a;
            }
            grid_barrier(bid);
        } else {
            // ---- last iteration: row pass + DCG fold ----
            float gs_r[8];
            #pragma unroll
            for (int mm = 0; mm < 8; mm++)
                gs_r[mm] = cs_r[mm] * (exp2f(target[tid * 8 + mm]) - 1.0f);
            for (int r = 0; r < cnt; r++) {
                uint4 q0 = reinterpret_cast<const uint4*>(g_mat + (size_t)(start + r) * NNV)[tid];
                float v0[8]; unpack8(q0, v0);
                float d1 = 0.0f, d2 = 0.0f;
                #pragma unroll
                for (int mm = 0; mm < 8; mm++) {
                    d1 = fmaf(v0[mm], cs_r[mm], d1);
                    d2 = fmaf(v0[mm], gs_r[mm], d2);
                }
                d1 = wredsum(d1); d2 = wredsum(d2);
                if (lane == 0) { s_pb[r][wid] = d1; s_pd[r][wid] = d2; }
            }
            __syncthreads();
            if (tid < cnt) {
                int i = start + tid;
                float b = 0.0f, d = 0.0f;
                #pragma unroll
                for (int k = 0; k < 16; k++) { b += s_pb[tid][k]; d += s_pd[tid][k]; }
                float Ro = g_R[i];
                float Rn = Ro / fmaxf(Ro * b, EPSF);
                g_rowdcg[i] = Rn * d / log2f((float)i + 2.0f);
            }
            grid_barrier(bid);
        }
    }

    // ================= FINAL ==============================================
    if (bid == 0) {
        float part = 0.0f;
        #pragma unroll
        for (int k = 0; k < 8; k++) part += __ldcg(&g_rowdcg[tid * 8 + k]);
        part = wredsum(part);
        if (lane == 0) s_red[wid] = part;
        float ip = (tid < NBLK) ? __ldcg(&g_idcgPart[tid]) : 0.0f;
        ip = wredsum(ip);
        if (lane == 0) s_red[16 + wid] = ip;
        __syncthreads();
        if (tid == 0) {
            float dcg = 0.0f, idcg = 0.0f;
            for (int k = 0; k < 16; k++) { dcg += s_red[k]; idcg += s_red[16 + k]; }
            out[0] = -(dcg / (idcg + 1e-8f));
        }
    }
}

extern "C" void kernel_launch(void* const* d_in, const int* in_sizes, int n_in,
                              void* d_out, int out_size) {
    const float* pred   = (const float*)d_in[0];
    const float* target = (const float*)d_in[1];
    float* out = (float*)d_out;
    ndcg_kernel<<<NBLK, TPB>>>(pred, target, out);
}

// round 9
// speedup vs baseline: 1.5355x; 1.0467x over previous
#include <cuda_runtime.h>
#include <cuda_bf16.h>
#include <math.h>

// NeuralNDCG, N=4096. Persistent kernel, 296 blocks (2/SM) x 512 threads.
// mat_t = diag(R) U diag(C); U = exp(c_i p_j - B_j - m_i) fixed.
// NEW: each block's 12 U-rows live in a 98KB smem tile (+2 rows in a global
// side buffer) -> row sweep is smem-resident, zero L2. U^T (32MB) stays in
// L2 for the col sweep. Uniform 14 rows/block via index clamping (full
// unroll). Mid-iteration barrier split into arrive/prefetch(U^T rows)/wait.

#define NNV 4096
#define NBLK 296
#define TPB 512
#define ROWS 14
#define SROWS 12
#define EPSF 1e-10f
#define ITERS 50
#define SMEM_BYTES (SROWS * NNV * 2 + (240 + 240 + 32) * 4)   // 100352

__device__ __nv_bfloat16 g_matT[(size_t)NNV * NNV];           // U^T (32 MB)
__device__ __nv_bfloat16 g_rext[(size_t)NBLK * 2 * NNV];      // rows 12,13 per block
__device__ float g_Bv[NNV], g_mv[NNV], g_R[NNV], g_a[NNV];
__device__ float g_C[2][NNV];
__device__ float g_rowdcg[NNV];
__device__ float g_idcgPart[NBLK];
__device__ unsigned g_leaf[37 * 32];
__device__ unsigned g_root;
__device__ volatile unsigned g_gen;

__device__ __forceinline__ unsigned grid_arrive(int bid, int tid) {
    __syncthreads();
    unsigned mygen = 0;
    if (tid == 0) {
        __threadfence();
        mygen = g_gen;
        unsigned l = (unsigned)(bid >> 3) * 32;                // 37 leaves x 8
        if (atomicAdd(&g_leaf[l], 1u) == 7) {
            atomicExch(&g_leaf[l], 0u);
            if (atomicAdd(&g_root, 1u) == 36) {
                atomicExch(&g_root, 0u);
                __threadfence();
                g_gen = mygen + 1;
            }
        }
    }
    return mygen;
}
__device__ __forceinline__ void grid_wait(unsigned mygen, int tid) {
    if (tid == 0) {
        while (g_gen == mygen) __nanosleep(32);
        __threadfence();
    }
    __syncthreads();
}
__device__ __forceinline__ void grid_barrier(int bid, int tid) {
    unsigned g = grid_arrive(bid, tid);
    grid_wait(g, tid);
}

__device__ __forceinline__ float wredsum(float v) {
    #pragma unroll
    for (int o = 16; o > 0; o >>= 1) v += __shfl_xor_sync(0xffffffffu, v, o);
    return v;
}
__device__ __forceinline__ float wredmax(float v) {
    #pragma unroll
    for (int o = 16; o > 0; o >>= 1) v = fmaxf(v, __shfl_xor_sync(0xffffffffu, v, o));
    return v;
}
__device__ __forceinline__ void unpack8(uint4 q, float* v) {
    const __nv_bfloat162* hh = reinterpret_cast<const __nv_bfloat162*>(&q);
    #pragma unroll
    for (int p = 0; p < 4; p++) {
        float2 f = __bfloat1622float2(hh[p]);
        v[2 * p] = f.x; v[2 * p + 1] = f.y;
    }
}
__device__ __forceinline__ float dot8(uint4 q, const float* w) {
    float v[8]; unpack8(q, v);
    float d = 0.0f;
    #pragma unroll
    for (int mm = 0; mm < 8; mm++) d = fmaf(v[mm], w[mm], d);
    return d;
}

__global__ void __launch_bounds__(TPB, 2)
ndcg_kernel(const float* __restrict__ pred, const float* __restrict__ target,
            float* __restrict__ out)
{
    extern __shared__ __align__(16) char dsm[];
    __nv_bfloat16* Ut = (__nv_bfloat16*)dsm;                 // 12 x 4096 bf16
    float* s_pb  = (float*)(dsm + SROWS * NNV * 2);          // [14*17] pad 240
    float* s_pd  = s_pb + 240;
    float* s_red = s_pd + 240;
    float* p_stage = (float*)dsm;                            // init only
    float* t_stage = p_stage + NNV;                          // init only

    const int tid = threadIdx.x, bid = blockIdx.x;
    const int wid = tid >> 5, lane = tid & 31;
    const int start = bid * ROWS;                            // clamped per-row

    // ================= INIT: C0=1; B[j]; ideal DCG =========================
    if (bid < 8) g_C[0][bid * TPB + tid] = 1.0f;
    for (int k = tid; k < NNV; k += TPB) { p_stage[k] = pred[k]; t_stage[k] = target[k]; }
    __syncthreads();
    if (wid < ROWS) {
        int j = min(start + wid, NNV - 1);
        bool v = (start + wid) < NNV;
        float pj = p_stage[j], tj = t_stage[j];
        float acc = 0.0f; int rank = 0;
        #pragma unroll 4
        for (int k = 0; k < 128; k++) {
            acc += fabsf(pj - p_stage[k * 32 + lane]);
            rank += (t_stage[k * 32 + lane] > tj);
        }
        acc = wredsum(acc);
        #pragma unroll
        for (int o = 16; o > 0; o >>= 1) rank += __shfl_xor_sync(0xffffffffu, rank, o);
        if (lane == 0) {
            if (v) g_Bv[j] = acc;
            s_red[wid] = v ? (exp2f(tj) - 1.0f) / log2f((float)rank + 2.0f) : 0.0f;
        }
    }
    __syncthreads();
    if (tid == 0) {
        float s = 0.0f;
        for (int k = 0; k < ROWS; k++) s += s_red[k];
        g_idcgPart[bid] = s;
    }
    grid_barrier(bid, tid);

    // ================= BUILD U rows -> smem tile / side buffer =============
    // (staging area is dead now; build reads pred/B from global, L2-served)
    if (wid < ROWS) {
        int i = min(start + wid, NNV - 1);
        bool v = (start + wid) < NNV;
        float ci = (float)(NNV - 1 - 2 * i);
        float m = -INFINITY;
        for (int c = 0; c < 16; c++) {
            int j0 = (c * 32 + lane) * 8;
            float4 p0 = __ldg((const float4*)(pred + j0));
            float4 p1 = __ldg((const float4*)(pred + j0 + 4));
            float4 b0 = __ldcg((const float4*)(g_Bv + j0));
            float4 b1 = __ldcg((const float4*)(g_Bv + j0 + 4));
            m = fmaxf(m, fmaf(ci, p0.x, -b0.x)); m = fmaxf(m, fmaf(ci, p0.y, -b0.y));
            m = fmaxf(m, fmaf(ci, p0.z, -b0.z)); m = fmaxf(m, fmaf(ci, p0.w, -b0.w));
            m = fmaxf(m, fmaf(ci, p1.x, -b1.x)); m = fmaxf(m, fmaf(ci, p1.y, -b1.y));
            m = fmaxf(m, fmaf(ci, p1.z, -b1.z)); m = fmaxf(m, fmaf(ci, p1.w, -b1.w));
        }
        m = wredmax(m);
        float z = 0.0f;
        for (int c = 0; c < 16; c++) {
            int j0 = (c * 32 + lane) * 8;
            float4 p0 = __ldg((const float4*)(pred + j0));
            float4 p1 = __ldg((const float4*)(pred + j0 + 4));
            float4 b0 = __ldcg((const float4*)(g_Bv + j0));
            float4 b1 = __ldcg((const float4*)(g_Bv + j0 + 4));
            float e[8];
            e[0] = __expf(fmaf(ci, p0.x, -b0.x) - m); e[1] = __expf(fmaf(ci, p0.y, -b0.y) - m);
            e[2] = __expf(fmaf(ci, p0.z, -b0.z) - m); e[3] = __expf(fmaf(ci, p0.w, -b0.w) - m);
            e[4] = __expf(fmaf(ci, p1.x, -b1.x) - m); e[5] = __expf(fmaf(ci, p1.y, -b1.y) - m);
            e[6] = __expf(fmaf(ci, p1.z, -b1.z) - m); e[7] = __expf(fmaf(ci, p1.w, -b1.w) - m);
            z += ((e[0] + e[1]) + (e[2] + e[3])) + ((e[4] + e[5]) + (e[6] + e[7]));
            uint4 q;
            __nv_bfloat162* hq = reinterpret_cast<__nv_bfloat162*>(&q);
            hq[0] = __floats2bfloat162_rn(e[0], e[1]);
            hq[1] = __floats2bfloat162_rn(e[2], e[3]);
            hq[2] = __floats2bfloat162_rn(e[4], e[5]);
            hq[3] = __floats2bfloat162_rn(e[6], e[7]);
            if (wid < SROWS)
                *(uint4*)(Ut + wid * NNV + j0) = q;
            else if (v)
                *(uint4*)(g_rext + ((size_t)bid * 2 + (wid - SROWS)) * NNV + j0) = q;
        }
        z = wredsum(z);
        if (lane == 0 && v) { g_mv[i] = m; g_R[i] = 1.0f / z; }
    }
    grid_barrier(bid, tid);

    // ================= BUILD U^T (column-wise recompute) + a0 ==============
    {
        float m_r[8], r0_r[8], ci_r[8];
        {
            const float4* mp = (const float4*)(g_mv + tid * 8);
            const float4* rp = (const float4*)(g_R + tid * 8);
            float4 m0 = __ldcg(mp), m1 = __ldcg(mp + 1);
            float4 r0 = __ldcg(rp), r1 = __ldcg(rp + 1);
            m_r[0]=m0.x; m_r[1]=m0.y; m_r[2]=m0.z; m_r[3]=m0.w;
            m_r[4]=m1.x; m_r[5]=m1.y; m_r[6]=m1.z; m_r[7]=m1.w;
            r0_r[0]=r0.x; r0_r[1]=r0.y; r0_r[2]=r0.z; r0_r[3]=r0.w;
            r0_r[4]=r1.x; r0_r[5]=r1.y; r0_r[6]=r1.z; r0_r[7]=r1.w;
        }
        #pragma unroll
        for (int mm = 0; mm < 8; mm++)
            ci_r[mm] = (float)(NNV - 1 - 2 * (tid * 8 + mm));
        #pragma unroll
        for (int r = 0; r < ROWS; r++) {
            int j = min(start + r, NNV - 1);
            bool v = (start + r) < NNV;
            float pj = __ldg(&pred[j]);
            float Bj = __ldcg(&g_Bv[j]);
            float e[8], d = 0.0f;
            #pragma unroll
            for (int mm = 0; mm < 8; mm++) {
                e[mm] = __expf(fmaf(ci_r[mm], pj, -Bj) - m_r[mm]);
                d = fmaf(r0_r[mm], e[mm], d);
            }
            uint4 q;
            __nv_bfloat162* hq = reinterpret_cast<__nv_bfloat162*>(&q);
            hq[0] = __floats2bfloat162_rn(e[0], e[1]);
            hq[1] = __floats2bfloat162_rn(e[2], e[3]);
            hq[2] = __floats2bfloat162_rn(e[4], e[5]);
            hq[3] = __floats2bfloat162_rn(e[6], e[7]);
            if (v) ((uint4*)(g_matT + (size_t)j * NNV))[tid] = q;
            d = wredsum(d);
            if (lane == 0) s_pb[r * 17 + wid] = d;
        }
        __syncthreads();
        if (tid < ROWS && start + tid < NNV) {
            float a = 0.0f;
            #pragma unroll
            for (int k = 0; k < 16; k++) a += s_pb[tid * 17 + k];
            g_a[start + tid] = a;
        }
    }
    grid_barrier(bid, tid);

    // ================= 50 SINKHORN ITERATIONS ==============================
    for (int t = 0; t < ITERS; t++) {
        const bool last = (t == ITERS - 1);
        const float* C_rd = g_C[t & 1];
        float* C_wr       = g_C[(t + 1) & 1];

        // C' for my 8 columns -> registers
        float cs_r[8];
        {
            const float4* cp = (const float4*)(C_rd + tid * 8);
            const float4* ap = (const float4*)(g_a + tid * 8);
            float4 c0 = __ldcg(cp), c1 = __ldcg(cp + 1);
            float4 a0 = __ldcg(ap), a1 = __ldcg(ap + 1);
            cs_r[0] = c0.x / fmaxf(c0.x * a0.x, EPSF);
            cs_r[1] = c0.y / fmaxf(c0.y * a0.y, EPSF);
            cs_r[2] = c0.z / fmaxf(c0.z * a0.z, EPSF);
            cs_r[3] = c0.w / fmaxf(c0.w * a0.w, EPSF);
            cs_r[4] = c1.x / fmaxf(c1.x * a1.x, EPSF);
            cs_r[5] = c1.y / fmaxf(c1.y * a1.y, EPSF);
            cs_r[6] = c1.z / fmaxf(c1.z * a1.z, EPSF);
            cs_r[7] = c1.w / fmaxf(c1.w * a1.w, EPSF);
        }
        if (!last && tid < ROWS && start + tid < NNV) {
            int j = start + tid;
            float Cj = __ldcg(&C_rd[j]), aj = __ldcg(&g_a[j]);
            C_wr[j] = Cj / fmaxf(Cj * aj, EPSF);
        }

        // ---- row sweep: 12 smem rows + 2 side rows (zero L2 for smem) ----
        uint4 q12 = ((const uint4*)(g_rext + (size_t)bid * 2 * NNV))[tid];
        uint4 q13 = ((const uint4*)(g_rext + ((size_t)bid * 2 + 1) * NNV))[tid];
        if (!last) {
            #pragma unroll
            for (int r = 0; r < SROWS; r++) {
                uint4 q = *(const uint4*)(Ut + r * NNV + tid * 8);
                float d = wredsum(dot8(q, cs_r));
                if (lane == 0) s_pb[r * 17 + wid] = d;
            }
            {
                float d = wredsum(dot8(q12, cs_r));
                if (lane == 0) s_pb[12 * 17 + wid] = d;
                d = wredsum(dot8(q13, cs_r));
                if (lane == 0) s_pb[13 * 17 + wid] = d;
            }
            __syncthreads();
            if (tid < ROWS && start + tid < NNV) {
                int i = start + tid;
                float b = 0.0f;
                #pragma unroll
                for (int k = 0; k < 16; k++) b += s_pb[tid * 17 + k];
                float Ro = g_R[i];
                g_R[i] = Ro / fmaxf(Ro * b, EPSF);
            }
            // ---- mid barrier; prefetch 4 U^T rows while others arrive ----
            unsigned mg = grid_arrive(bid, tid);
            uint4 pf0 = ((const uint4*)(g_matT + (size_t)min(start + 0, NNV - 1) * NNV))[tid];
            uint4 pf1 = ((const uint4*)(g_matT + (size_t)min(start + 1, NNV - 1) * NNV))[tid];
            uint4 pf2 = ((const uint4*)(g_matT + (size_t)min(start + 2, NNV - 1) * NNV))[tid];
            uint4 pf3 = ((const uint4*)(g_matT + (size_t)min(start + 3, NNV - 1) * NNV))[tid];
            grid_wait(mg, tid);

            // ---- col sweep over U^T (L2) with fresh R ----
            float rs_r[8];
            {
                const float4* rp = (const float4*)(g_R + tid * 8);
                float4 r0 = __ldcg(rp), r1 = __ldcg(rp + 1);
                rs_r[0]=r0.x; rs_r[1]=r0.y; rs_r[2]=r0.z; rs_r[3]=r0.w;
                rs_r[4]=r1.x; rs_r[5]=r1.y; rs_r[6]=r1.z; rs_r[7]=r1.w;
            }
            {
                float d0 = wredsum(dot8(pf0, rs_r));
                float d1 = wredsum(dot8(pf1, rs_r));
                float d2 = wredsum(dot8(pf2, rs_r));
                float d3 = wredsum(dot8(pf3, rs_r));
                if (lane == 0) {
                    s_pb[0 * 17 + wid] = d0; s_pb[1 * 17 + wid] = d1;
                    s_pb[2 * 17 + wid] = d2; s_pb[3 * 17 + wid] = d3;
                }
            }
            #pragma unroll
            for (int r = 4; r < ROWS; r++) {
                uint4 q = ((const uint4*)(g_matT + (size_t)min(start + r, NNV - 1) * NNV))[tid];
                float d = wredsum(dot8(q, rs_r));
                if (lane == 0) s_pb[r * 17 + wid] = d;
            }
            __syncthreads();
            if (tid < ROWS && start + tid < NNV) {
                float a = 0.0f;
                #pragma unroll
                for (int k = 0; k < 16; k++) a += s_pb[tid * 17 + k];
                g_a[start + tid] = a;
            }
            grid_barrier(bid, tid);
        } else {
            // ---- last iteration: row sweep + DCG fold, no col sweep ----
            float gs_r[8];
            #pragma unroll
            for (int mm = 0; mm < 8; mm++)
                gs_r[mm] = cs_r[mm] * (exp2f(target[tid * 8 + mm]) - 1.0f);
            #pragma unroll
            for (int r = 0; r < SROWS; r++) {
                uint4 q = *(const uint4*)(Ut + r * NNV + tid * 8);
                float d1 = wredsum(dot8(q, cs_r));
                float d2 = wredsum(dot8(q, gs_r));
                if (lane == 0) { s_pb[r * 17 + wid] = d1; s_pd[r * 17 + wid] = d2; }
            }
            {
                float d1 = wredsum(dot8(q12, cs_r));
                float d2 = wredsum(dot8(q12, gs_r));
                if (lane == 0) { s_pb[12 * 17 + wid] = d1; s_pd[12 * 17 + wid] = d2; }
                d1 = wredsum(dot8(q13, cs_r));
                d2 = wredsum(dot8(q13, gs_r));
                if (lane == 0) { s_pb[13 * 17 + wid] = d1; s_pd[13 * 17 + wid] = d2; }
            }
            __syncthreads();
            if (tid < ROWS && start + tid < NNV) {
                int i = start + tid;
                float b = 0.0f, d = 0.0f;
                #pragma unroll
                for (int k = 0; k < 16; k++) {
                    b += s_pb[tid * 17 + k];
                    d += s_pd[tid * 17 + k];
                }
                float Ro = g_R[i];
                float Rn = Ro / fmaxf(Ro * b, EPSF);
                g_rowdcg[i] = Rn * d / log2f((float)i + 2.0f);
            }
            grid_barrier(bid, tid);
        }
    }

    // ================= FINAL ==============================================
    if (bid == 0) {
        float part = 0.0f;
        #pragma unroll
        for (int k = 0; k < 8; k++) part += __ldcg(&g_rowdcg[tid * 8 + k]);
        part = wredsum(part);
        if (lane == 0) s_red[wid] = part;
        float ip = (tid < NBLK) ? __ldcg(&g_idcgPart[tid]) : 0.0f;
        ip = wredsum(ip);
        if (lane == 0) s_red[16 + wid] = ip;
        __syncthreads();
        if (tid == 0) {
            float dcg = 0.0f, idcg = 0.0f;
            for (int k = 0; k < 16; k++) { dcg += s_red[k]; idcg += s_red[16 + k]; }
            out[0] = -(dcg / (idcg + 1e-8f));
        }
    }
}

extern "C" void kernel_launch(void* const* d_in, const int* in_sizes, int n_in,
                              void* d_out, int out_size) {
    const float* pred   = (const float*)d_in[0];
    const float* target = (const float*)d_in[1];
    float* out = (float*)d_out;
    cudaFuncSetAttribute(ndcg_kernel, cudaFuncAttributeMaxDynamicSharedMemorySize,
                         SMEM_BYTES);
    ndcg_kernel<<<NBLK, TPB, SMEM_BYTES>>>(pred, target, out);
}

// round 12
// speedup vs baseline: 1.6178x; 1.0536x over previous
#include <cuda_runtime.h>
#include <cuda_bf16.h>
#include <math.h>

// NeuralNDCG, N=4096. Persistent kernel, 296 blocks (2/SM) x 512 threads.
// Proven math (R8/R9): mat_t = diag(R) U diag(C'); U and U^T both in global
// bf16 (64MB, L2-resident, read-only). Per iteration: batched row sweep over
// U (b_i -> R') [barrier] batched col sweep over U^T (a_s -> C') [barrier].
// NEW: sweep loads issued in batches of 5/5/4 with independent shfl-reduce
// chains -- collapses the per-warp serial (load->reduce)x14 critical path.

#define NNV 4096
#define NBLK 296
#define TPB 512
#define ROWS 14
#define EPSF 1e-10f
#define ITERS 50

__device__ __nv_bfloat16 g_U [(size_t)NNV * NNV];   // 32 MB
__device__ __nv_bfloat16 g_UT[(size_t)NNV * NNV];   // 32 MB
__device__ float g_Bv[NNV], g_mv[NNV], g_R[NNV], g_Cp[NNV];
__device__ float g_rowdcg[NNV];
__device__ float g_idcgPart[NBLK];
__device__ unsigned g_leaf[37 * 32];
__device__ unsigned g_root;
__device__ volatile unsigned g_gen;

__device__ __forceinline__ void grid_barrier(int bid, int tid) {
    __syncthreads();
    if (tid == 0) {
        __threadfence();
        unsigned mygen = g_gen;
        unsigned l = (unsigned)(bid >> 3) * 32;       // 37 leaves x 8 blocks
        if (atomicAdd(&g_leaf[l], 1u) == 7) {
            atomicExch(&g_leaf[l], 0u);
            if (atomicAdd(&g_root, 1u) == 36) {
                atomicExch(&g_root, 0u);
                __threadfence();
                g_gen = mygen + 1;
            }
        }
        while (g_gen == mygen) __nanosleep(32);
        __threadfence();
    }
    __syncthreads();
}

__device__ __forceinline__ float wredsum(float v) {
    #pragma unroll
    for (int o = 16; o > 0; o >>= 1) v += __shfl_xor_sync(0xffffffffu, v, o);
    return v;
}
__device__ __forceinline__ float wredmax(float v) {
    #pragma unroll
    for (int o = 16; o > 0; o >>= 1) v = fmaxf(v, __shfl_xor_sync(0xffffffffu, v, o));
    return v;
}
__device__ __forceinline__ float dot8(uint4 q, const float* w) {
    const __nv_bfloat162* hh = reinterpret_cast<const __nv_bfloat162*>(&q);
    float d = 0.0f;
    #pragma unroll
    for (int p = 0; p < 4; p++) {
        float2 f = __bfloat1622float2(hh[p]);
        d = fmaf(f.x, w[2 * p], d);
        d = fmaf(f.y, w[2 * p + 1], d);
    }
    return d;
}

__global__ void __launch_bounds__(TPB, 2)
ndcg_kernel(const float* __restrict__ pred, const float* __restrict__ target,
            float* __restrict__ out)
{
    __shared__ float p_s[NNV];             // pred (persists)
    __shared__ float t_s[NNV];             // target, then B
    __shared__ float s_pb[ROWS * 17];
    __shared__ float s_pd[ROWS * 17];
    __shared__ float s_red[32];

    const int tid = threadIdx.x, bid = blockIdx.x;
    const int wid = tid >> 5, lane = tid & 31;
    const int start = bid * ROWS;
    const int myi = start + wid;
    const bool vown = (wid < ROWS) && (myi < NNV);

    // ================= PHASE 0: B[j], ideal DCG ============================
    for (int k = tid; k < NNV; k += TPB) { p_s[k] = pred[k]; t_s[k] = target[k]; }
    if (wid < ROWS && lane == 0) s_red[wid] = 0.0f;
    __syncthreads();
    if (vown) {
        float pj = p_s[myi], tj = t_s[myi];
        float acc = 0.0f; int trank = 0;
        #pragma unroll 4
        for (int k = 0; k < 128; k++) {
            acc += fabsf(pj - p_s[k * 32 + lane]);
            trank += (t_s[k * 32 + lane] > tj);
        }
        acc = wredsum(acc);
        #pragma unroll
        for (int o = 16; o > 0; o >>= 1) trank += __shfl_xor_sync(0xffffffffu, trank, o);
        if (lane == 0) {
            g_Bv[myi] = acc;
            s_red[wid] = (exp2f(tj) - 1.0f) / log2f((float)trank + 2.0f);
        }
    }
    __syncthreads();
    if (tid == 0) {
        float s = 0.0f;
        for (int k = 0; k < ROWS; k++) s += s_red[k];
        g_idcgPart[bid] = s;
    }
    grid_barrier(bid, tid);

    // ================= PHASE 1: build U rows, m_i, R0 ======================
    for (int k = tid; k < NNV; k += TPB) t_s[k] = __ldcg(&g_Bv[k]);   // B -> t_s
    __syncthreads();
    if (vown) {
        const int i = myi;
        const float ci = (float)(NNV - 1 - 2 * i);
        float m = -INFINITY;
        for (int c = 0; c < 16; c++) {
            int j0 = (c * 32 + lane) * 8;
            #pragma unroll
            for (int mm = 0; mm < 8; mm++)
                m = fmaxf(m, fmaf(ci, p_s[j0 + mm], -t_s[j0 + mm]));
        }
        m = wredmax(m);
        float z = 0.0f;
        uint4* rq = reinterpret_cast<uint4*>(g_U + (size_t)i * NNV);
        for (int c = 0; c < 16; c++) {
            int j0 = (c * 32 + lane) * 8;
            float e[8];
            #pragma unroll
            for (int mm = 0; mm < 8; mm++) {
                e[mm] = __expf(fmaf(ci, p_s[j0 + mm], -t_s[j0 + mm]) - m);
                z += e[mm];
            }
            uint4 q;
            __nv_bfloat162* hq = reinterpret_cast<__nv_bfloat162*>(&q);
            hq[0] = __floats2bfloat162_rn(e[0], e[1]);
            hq[1] = __floats2bfloat162_rn(e[2], e[3]);
            hq[2] = __floats2bfloat162_rn(e[4], e[5]);
            hq[3] = __floats2bfloat162_rn(e[6], e[7]);
            rq[c * 32 + lane] = q;
        }
        z = wredsum(z);
        if (lane == 0) { g_mv[i] = m; g_R[i] = 1.0f / z; }
    }
    grid_barrier(bid, tid);

    // ================= PHASE 2: build U^T rows + a0 -> C'1 =================
    {
        float m_r[8], r0_r[8], ci_r[8];
        {
            const float4* mp = (const float4*)(g_mv + tid * 8);
            const float4* rp = (const float4*)(g_R + tid * 8);
            float4 m0 = __ldcg(mp), m1 = __ldcg(mp + 1);
            float4 r0 = __ldcg(rp), r1 = __ldcg(rp + 1);
            m_r[0]=m0.x; m_r[1]=m0.y; m_r[2]=m0.z; m_r[3]=m0.w;
            m_r[4]=m1.x; m_r[5]=m1.y; m_r[6]=m1.z; m_r[7]=m1.w;
            r0_r[0]=r0.x; r0_r[1]=r0.y; r0_r[2]=r0.z; r0_r[3]=r0.w;
            r0_r[4]=r1.x; r0_r[5]=r1.y; r0_r[6]=r1.z; r0_r[7]=r1.w;
        }
        #pragma unroll
        for (int mm = 0; mm < 8; mm++)
            ci_r[mm] = (float)(NNV - 1 - 2 * (tid * 8 + mm));
        #pragma unroll
        for (int r = 0; r < ROWS; r++) {
            int j = min(start + r, NNV - 1);
            bool v = (start + r) < NNV;
            float pj = p_s[j], Bj = t_s[j];
            float e[8], d = 0.0f;
            #pragma unroll
            for (int mm = 0; mm < 8; mm++) {
                e[mm] = __expf(fmaf(ci_r[mm], pj, -Bj) - m_r[mm]);
                d = fmaf(r0_r[mm], e[mm], d);
            }
            uint4 q;
            __nv_bfloat162* hq = reinterpret_cast<__nv_bfloat162*>(&q);
            hq[0] = __floats2bfloat162_rn(e[0], e[1]);
            hq[1] = __floats2bfloat162_rn(e[2], e[3]);
            hq[2] = __floats2bfloat162_rn(e[4], e[5]);
            hq[3] = __floats2bfloat162_rn(e[6], e[7]);
            if (v) ((uint4*)(g_UT + (size_t)j * NNV))[tid] = q;
            d = wredsum(d);
            if (lane == 0) s_pb[r * 17 + wid] = d;
        }
        __syncthreads();
        if (tid < ROWS && start + tid < NNV) {
            float a = 0.0f;
            #pragma unroll
            for (int k = 0; k < 16; k++) a += s_pb[tid * 17 + k];
            g_Cp[start + tid] = 1.0f / fmaxf(a, EPSF);    // C0 = 1
        }
    }
    grid_barrier(bid, tid);

    // ================= 50 SINKHORN ITERATIONS ==============================
    for (int t = 0; t < ITERS; t++) {
        const bool last = (t == ITERS - 1);

        // C' for my 8 columns -> registers
        float cs_r[8];
        {
            const float4* cp = (const float4*)(g_Cp + tid * 8);
            float4 c0 = __ldcg(cp), c1 = __ldcg(cp + 1);
            cs_r[0]=c0.x; cs_r[1]=c0.y; cs_r[2]=c0.z; cs_r[3]=c0.w;
            cs_r[4]=c1.x; cs_r[5]=c1.y; cs_r[6]=c1.z; cs_r[7]=c1.w;
        }

        if (!last) {
            // ---- row sweep over U: batched loads (5,5,4) ----
            #pragma unroll
            for (int g = 0; g < 3; g++) {
                const int r0 = g * 5, B = (g < 2) ? 5 : 4;
                uint4 q[5];
                #pragma unroll
                for (int b = 0; b < 5; b++) if (b < B)
                    q[b] = ((const uint4*)(g_U + (size_t)min(start + r0 + b, NNV - 1) * NNV))[tid];
                #pragma unroll
                for (int b = 0; b < 5; b++) if (b < B) {
                    float d = wredsum(dot8(q[b], cs_r));
                    if (lane == 0) s_pb[(r0 + b) * 17 + wid] = d;
                }
            }
            __syncthreads();
            if (tid < ROWS && start + tid < NNV) {
                int i = start + tid;
                float b = 0.0f;
                #pragma unroll
                for (int k = 0; k < 16; k++) b += s_pb[tid * 17 + k];
                float Ro = g_R[i];
                g_R[i] = Ro / fmaxf(Ro * b, EPSF);
            }
            grid_barrier(bid, tid);

            // ---- col sweep over U^T: batched loads (5,5,4) ----
            float rs_r[8];
            {
                const float4* rp = (const float4*)(g_R + tid * 8);
                float4 r0 = __ldcg(rp), r1 = __ldcg(rp + 1);
                rs_r[0]=r0.x; rs_r[1]=r0.y; rs_r[2]=r0.z; rs_r[3]=r0.w;
                rs_r[4]=r1.x; rs_r[5]=r1.y; rs_r[6]=r1.z; rs_r[7]=r1.w;
            }
            #pragma unroll
            for (int g = 0; g < 3; g++) {
                const int r0 = g * 5, B = (g < 2) ? 5 : 4;
                uint4 q[5];
                #pragma unroll
                for (int b = 0; b < 5; b++) if (b < B)
                    q[b] = ((const uint4*)(g_UT + (size_t)min(start + r0 + b, NNV - 1) * NNV))[tid];
                #pragma unroll
                for (int b = 0; b < 5; b++) if (b < B) {
                    float d = wredsum(dot8(q[b], rs_r));
                    if (lane == 0) s_pb[(r0 + b) * 17 + wid] = d;
                }
            }
            __syncthreads();
            if (tid < ROWS && start + tid < NNV) {
                int s = start + tid;
                float a = 0.0f;
                #pragma unroll
                for (int k = 0; k < 16; k++) a += s_pb[tid * 17 + k];
                float Co = __ldcg(&g_Cp[s]);
                g_Cp[s] = Co / fmaxf(Co * a, EPSF);
            }
            grid_barrier(bid, tid);
        } else {
            // ---- last iteration: row sweep + DCG fold ----
            float gs_r[8];
            #pragma unroll
            for (int mm = 0; mm < 8; mm++)
                gs_r[mm] = cs_r[mm] * (exp2f(target[tid * 8 + mm]) - 1.0f);
            #pragma unroll
            for (int g = 0; g < 3; g++) {
                const int r0 = g * 5, B = (g < 2) ? 5 : 4;
                uint4 q[5];
                #pragma unroll
                for (int b = 0; b < 5; b++) if (b < B)
                    q[b] = ((const uint4*)(g_U + (size_t)min(start + r0 + b, NNV - 1) * NNV))[tid];
                #pragma unroll
                for (int b = 0; b < 5; b++) if (b < B) {
                    float d1 = wredsum(dot8(q[b], cs_r));
                    float d2 = wredsum(dot8(q[b], gs_r));
                    if (lane == 0) {
                        s_pb[(r0 + b) * 17 + wid] = d1;
                        s_pd[(r0 + b) * 17 + wid] = d2;
                    }
                }
            }
            __syncthreads();
            if (tid < ROWS && start + tid < NNV) {
                int i = start + tid;
                float b = 0.0f, d = 0.0f;
                #pragma unroll
                for (int k = 0; k < 16; k++) {
                    b += s_pb[tid * 17 + k];
                    d += s_pd[tid * 17 + k];
                }
                float Ro = g_R[i];
                float Rn = Ro / fmaxf(Ro * b, EPSF);
                g_rowdcg[i] = Rn * d / log2f((float)i + 2.0f);
            }
            grid_barrier(bid, tid);
        }
    }

    // ================= FINAL ==============================================
    if (bid == 0) {
        float part = 0.0f;
        #pragma unroll
        for (int k = 0; k < 8; k++) part += __ldcg(&g_rowdcg[tid * 8 + k]);
        part = wredsum(part);
        if (lane == 0) s_red[wid] = part;
        float ip = (tid < NBLK) ? __ldcg(&g_idcgPart[tid]) : 0.0f;
        ip = wredsum(ip);
        if (lane == 0) s_red[16 + wid] = ip;
        __syncthreads();
        if (tid == 0) {
            float dcg = 0.0f, idcg = 0.0f;
            for (int k = 0; k < 16; k++) { dcg += s_red[k]; idcg += s_red[16 + k]; }
            out[0] = -(dcg / (idcg + 1e-8f));
        }
    }
}

extern "C" void kernel_launch(void* const* d_in, const int* in_sizes, int n_in,
                              void* d_out, int out_size) {
    const float* pred   = (const float*)d_in[0];
    const float* target = (const float*)d_in[1];
    float* out = (float*)d_out;
    ndcg_kernel<<<NBLK, TPB>>>(pred, target, out);
}